// round 8
// baseline (speedup 1.0000x reference)
#include <cuda_runtime.h>

#define NTHR 256
#define NBLK 888                          // 6 blocks/SM x 148 SMs (persistent)
#define V4_PER_LANE 8
#define CHUNK_V4 (32 * V4_PER_LANE)       // 256 float4 = 1024 elements per chunk
#define MAX_CHUNKS 32768                  // nvec = 2^23 -> exactly 32768 chunks

// Chunk-indexed partials: value at g_chunk[c] is independent of WHICH warp
// computed it -> dynamic scheduling, deterministic output.
__device__ float        g_chunk[MAX_CHUNKS];
__device__ float        g_extra;          // remainder region partial (block 0)
__device__ unsigned int g_steal = 0;      // work-stealing counter (self-reset)
__device__ unsigned int g_count = 0;      // block completion (wraps via atomicInc)

// Raw MUFU.LG2 — inputs guaranteed in [1e-4, 1-1e-4] (always normal).
__device__ __forceinline__ float lg2_raw(float x) {
    float r;
    asm("lg2.approx.ftz.f32 %0, %1;" : "=f"(r) : "f"(x));
    return r;
}

// Binary KL in log2 units (sum scaled by ln2 once at the very end).
__device__ __forceinline__ void kl2_acc(float p, float q, float& acc) {
    float omp = 1.0f - p;
    float omq = 1.0f - q;
    float d1  = lg2_raw(p)   - lg2_raw(q);
    float d2  = lg2_raw(omp) - lg2_raw(omq);
    acc = fmaf(p,   d1, acc);
    acc = fmaf(omp, d2, acc);
}

__device__ __forceinline__ void kl2_vec4(float4 a, float4 b, float& acc) {
    kl2_acc(a.x, b.x, acc);
    kl2_acc(a.y, b.y, acc);
    kl2_acc(a.z, b.z, acc);
    kl2_acc(a.w, b.w, acc);
}

__global__ void __launch_bounds__(NTHR, 6)
kl_fused(const float* __restrict__ p, const float* __restrict__ q,
         int n, float* __restrict__ out) {
    const int nvec = n >> 2;
    int nchunks = nvec / CHUNK_V4;
    if (nchunks > MAX_CHUNKS) nchunks = MAX_CHUNKS;

    const float4* __restrict__ p4 = reinterpret_cast<const float4*>(p);
    const float4* __restrict__ q4 = reinterpret_cast<const float4*>(q);

    const int tid  = threadIdx.x;
    const int lane = tid & 31;

    // ---- Remainder region (beyond chunk coverage + scalar tail): block 0 ----
    // Empty at N=2^25; deterministic (fixed thread->element map, fixed order).
    if (blockIdx.x == 0) {
        float racc = 0.0f;
        for (int i = nchunks * CHUNK_V4 + tid; i < nvec; i += NTHR)
            kl2_vec4(__ldcs(&p4[i]), __ldcs(&q4[i]), racc);
        for (int i = (nvec << 2) + tid; i < n; i += NTHR)
            kl2_acc(p[i], q[i], racc);
        // Block reduce (fixed shfl tree -> deterministic)
        #pragma unroll
        for (int o = 16; o > 0; o >>= 1)
            racc += __shfl_down_sync(0xffffffffu, racc, o);
        __shared__ float rs[NTHR / 32];
        if (lane == 0) rs[tid >> 5] = racc;
        __syncthreads();
        if (tid == 0) {
            float t = 0.0f;
            #pragma unroll
            for (int w = 0; w < NTHR / 32; w++) t += rs[w];
            g_extra = t;
        }
        __syncthreads();
    }

    // ---- Dynamic warp-level work stealing over chunks ----
    // Fast SMs grab more chunks; all blocks finish together -> no straggler
    // tail degrading average DRAM utilization.
    for (;;) {
        unsigned int c;
        if (lane == 0) c = atomicAdd(&g_steal, 1u);
        c = __shfl_sync(0xffffffffu, c, 0);
        if (c >= (unsigned int)nchunks) break;

        int base = (int)c * CHUNK_V4 + lane;
        float acc2 = 0.0f;
        #pragma unroll
        for (int j = 0; j < V4_PER_LANE; j += 2) {
            float4 a0 = __ldcs(&p4[base + (j + 0) * 32]);
            float4 a1 = __ldcs(&p4[base + (j + 1) * 32]);
            float4 b0 = __ldcs(&q4[base + (j + 0) * 32]);
            float4 b1 = __ldcs(&q4[base + (j + 1) * 32]);
            kl2_vec4(a0, b0, acc2);
            kl2_vec4(a1, b1, acc2);
        }
        // Warp reduce (fixed tree) -> chunk partial, deterministic per chunk.
        #pragma unroll
        for (int o = 16; o > 0; o >>= 1)
            acc2 += __shfl_down_sync(0xffffffffu, acc2, o);
        if (lane == 0) g_chunk[c] = acc2;
    }

    // Publish this thread's global writes, then signal block completion.
    __threadfence();
    __syncthreads();

    __shared__ bool is_last;
    if (tid == 0) {
        // atomicInc wraps to 0 at gridDim.x-1 -> self-resetting across replays.
        unsigned int done = atomicInc(&g_count, gridDim.x - 1);
        is_last = (done == gridDim.x - 1);
    }
    __syncthreads();

    if (is_last) {
        __threadfence();   // acquire side: see all blocks' chunk writes
        // Fixed-order reduce over chunk partials (deterministic).
        float fs = 0.0f;
        for (int i = tid; i < nchunks; i += NTHR)
            fs += g_chunk[i];
        double d = (double)fs;
        #pragma unroll
        for (int o = 16; o > 0; o >>= 1)
            d += __shfl_down_sync(0xffffffffu, d, o);
        __shared__ double sd[NTHR / 32];
        if (lane == 0) sd[tid >> 5] = d;
        __syncthreads();
        if (tid == 0) {
            double t = 0.0;
            #pragma unroll
            for (int w = 0; w < NTHR / 32; w++) t += sd[w];
            t += (double)g_extra;
            out[0] = (float)(t * 0.6931471805599453);  // log2 -> ln
            g_steal = 0;                                // reset for next replay
        }
    }
}

extern "C" void kernel_launch(void* const* d_in, const int* in_sizes, int n_in,
                              void* d_out, int out_size) {
    const float* p = (const float*)d_in[0];
    const float* q = (const float*)d_in[1];
    float* out = (float*)d_out;
    int n = in_sizes[0];

    kl_fused<<<NBLK, NTHR>>>(p, q, n, out);
}

// round 9
// speedup vs baseline: 1.1642x; 1.1642x over previous
#include <cuda_runtime.h>
#include <cstdint>

#define NTHR 256
#define NBLK 888                    // 6 blocks/SM x 148 SMs, persistent
#define NSTAGE 2
#define TILE_V4 512                 // 512 float4 = 8 KB per input per stage
#define TILE_BYTES (TILE_V4 * 16)   // 8192
#define CHUNK_ELEMS (TILE_V4 * 4)   // 2048 elements per chunk

__device__ float        g_partials[NBLK];
__device__ unsigned int g_count = 0;

// ---- PTX helpers -----------------------------------------------------------
__device__ __forceinline__ uint32_t smem_u32(const void* p) {
    return (uint32_t)__cvta_generic_to_shared(p);
}
__device__ __forceinline__ void mbar_init(uint32_t a, uint32_t cnt) {
    asm volatile("mbarrier.init.shared.b64 [%0], %1;" :: "r"(a), "r"(cnt) : "memory");
}
__device__ __forceinline__ void mbar_expect_tx(uint32_t a, uint32_t bytes) {
    asm volatile("mbarrier.arrive.expect_tx.shared.b64 _, [%0], %1;"
                 :: "r"(a), "r"(bytes) : "memory");
}
__device__ __forceinline__ void mbar_wait(uint32_t a, uint32_t parity) {
    asm volatile(
        "{\n\t"
        ".reg .pred P;\n\t"
        "WL_%=:\n\t"
        "mbarrier.try_wait.parity.acquire.cta.shared::cta.b64 P, [%0], %1, 0x989680;\n\t"
        "@P bra.uni WD_%=;\n\t"
        "bra.uni WL_%=;\n\t"
        "WD_%=:\n\t"
        "}" :: "r"(a), "r"(parity) : "memory");
}
__device__ __forceinline__ void bulk_g2s(uint32_t dst, const void* src,
                                         uint32_t bytes, uint32_t mbar) {
    asm volatile(
        "cp.async.bulk.shared::cta.global.mbarrier::complete_tx::bytes [%0], [%1], %2, [%3];"
        :: "r"(dst), "l"(src), "r"(bytes), "r"(mbar) : "memory");
}

// ---- math ------------------------------------------------------------------
// Raw MUFU.LG2 — inputs guaranteed in [1e-4, 1-1e-4] (always normal).
__device__ __forceinline__ float lg2_raw(float x) {
    float r;
    asm("lg2.approx.ftz.f32 %0, %1;" : "=f"(r) : "f"(x));
    return r;
}
// Binary KL in log2 units (sum scaled by ln2 once at the very end).
__device__ __forceinline__ void kl2_acc(float p, float q, float& acc) {
    float omp = 1.0f - p;
    float omq = 1.0f - q;
    float d1  = lg2_raw(p)   - lg2_raw(q);
    float d2  = lg2_raw(omp) - lg2_raw(omq);
    acc = fmaf(p,   d1, acc);
    acc = fmaf(omp, d2, acc);
}
__device__ __forceinline__ void kl2_vec4(float4 a, float4 b, float& acc) {
    kl2_acc(a.x, b.x, acc);
    kl2_acc(a.y, b.y, acc);
    kl2_acc(a.z, b.z, acc);
    kl2_acc(a.w, b.w, acc);
}

// ---- kernel ----------------------------------------------------------------
__global__ void __launch_bounds__(NTHR, 6)
kl_fused(const float* __restrict__ p, const float* __restrict__ q,
         int n, float* __restrict__ out) {
    const int nvec    = n >> 2;
    const int nchunks = nvec / TILE_V4;     // 16384 at N=2^25

    const float4* __restrict__ p4 = reinterpret_cast<const float4*>(p);
    const float4* __restrict__ q4 = reinterpret_cast<const float4*>(q);

    __shared__ float4 bufP[NSTAGE][TILE_V4];   // 16 KB
    __shared__ float4 bufQ[NSTAGE][TILE_V4];   // 16 KB
    __shared__ __align__(8) unsigned long long mbar[NSTAGE];

    const int tid  = threadIdx.x;
    const int lane = tid & 31;

    if (tid == 0) {
        mbar_init(smem_u32(&mbar[0]), 1);
        mbar_init(smem_u32(&mbar[1]), 1);
    }
    __syncthreads();

    // Static chunk->block map: block b owns chunks b, b+NBLK, ... (deterministic)
    const int myfirst = blockIdx.x;
    const int m = (myfirst < nchunks) ? (nchunks - myfirst + NBLK - 1) / NBLK : 0;

    float acc = 0.0f;   // log2 units

    // Prologue: fill both stages.
    if (tid == 0) {
        #pragma unroll
        for (int s = 0; s < NSTAGE; s++) {
            if (s < m) {
                long c = (long)myfirst + (long)s * NBLK;
                uint32_t mb = smem_u32(&mbar[s]);
                mbar_expect_tx(mb, 2 * TILE_BYTES);
                bulk_g2s(smem_u32(&bufP[s][0]), p4 + c * TILE_V4, TILE_BYTES, mb);
                bulk_g2s(smem_u32(&bufQ[s][0]), q4 + c * TILE_V4, TILE_BYTES, mb);
            }
        }
    }

    int ph0 = 0, ph1 = 0;   // per-stage phase parity
    for (int j = 0; j < m; j++) {
        const int s = j & 1;
        uint32_t mb = smem_u32(&mbar[s]);
        if (s == 0) { mbar_wait(mb, ph0); ph0 ^= 1; }
        else        { mbar_wait(mb, ph1); ph1 ^= 1; }

        // Consume 8 KB + 8 KB: 2 float4 per input per thread, conflict-free.
        float4 a0 = bufP[s][tid];
        float4 a1 = bufP[s][tid + NTHR];
        float4 b0 = bufQ[s][tid];
        float4 b1 = bufQ[s][tid + NTHR];
        kl2_vec4(a0, b0, acc);
        kl2_vec4(a1, b1, acc);

        __syncthreads();   // everyone consumed stage s -> safe to overwrite

        if (tid == 0 && (j + NSTAGE) < m) {
            long c = (long)myfirst + (long)(j + NSTAGE) * NBLK;
            mbar_expect_tx(mb, 2 * TILE_BYTES);
            bulk_g2s(smem_u32(&bufP[s][0]), p4 + c * TILE_V4, TILE_BYTES, mb);
            bulk_g2s(smem_u32(&bufQ[s][0]), q4 + c * TILE_V4, TILE_BYTES, mb);
        }
    }

    // Remainder float4s + scalar tail (none at N=2^25): last block, via LDG.
    if (blockIdx.x == gridDim.x - 1) {
        for (int i = nchunks * TILE_V4 + tid; i < nvec; i += NTHR)
            kl2_vec4(__ldcs(&p4[i]), __ldcs(&q4[i]), acc);
        for (int i = (nvec << 2) + tid; i < n; i += NTHR)
            kl2_acc(p[i], q[i], acc);
    }

    acc *= 0.6931471805599453f;   // log2 -> ln, once per thread

    // Block reduce (fixed tree -> deterministic)
    #pragma unroll
    for (int o = 16; o > 0; o >>= 1)
        acc += __shfl_down_sync(0xffffffffu, acc, o);
    __shared__ float s_red[NTHR / 32];
    if (lane == 0) s_red[tid >> 5] = acc;
    __syncthreads();
    float bsum = 0.0f;
    if (tid < 32) {
        bsum = (tid < NTHR / 32) ? s_red[tid] : 0.0f;
        #pragma unroll
        for (int o = (NTHR / 64); o > 0; o >>= 1)
            bsum += __shfl_down_sync(0xffffffffu, bsum, o);
    }

    __shared__ bool is_last;
    if (tid == 0) {
        g_partials[blockIdx.x] = bsum;
        __threadfence();
        // atomicInc wraps to 0 at gridDim.x-1 -> self-resetting, graph-replay safe.
        unsigned int done = atomicInc(&g_count, gridDim.x - 1);
        is_last = (done == gridDim.x - 1);
    }
    __syncthreads();

    if (is_last) {
        // Deterministic fixed-order final reduce in fp64.
        double dacc = 0.0;
        for (int i = tid; i < gridDim.x; i += NTHR)
            dacc += (double)g_partials[i];
        #pragma unroll
        for (int o = 16; o > 0; o >>= 1)
            dacc += __shfl_down_sync(0xffffffffu, dacc, o);
        __shared__ double sd[NTHR / 32];
        if (lane == 0) sd[tid >> 5] = dacc;
        __syncthreads();
        if (tid == 0) {
            double t = 0.0;
            #pragma unroll
            for (int w = 0; w < NTHR / 32; w++) t += sd[w];
            out[0] = (float)t;
        }
    }
}

extern "C" void kernel_launch(void* const* d_in, const int* in_sizes, int n_in,
                              void* d_out, int out_size) {
    const float* p = (const float*)d_in[0];
    const float* q = (const float*)d_in[1];
    float* out = (float*)d_out;
    int n = in_sizes[0];

    kl_fused<<<NBLK, NTHR>>>(p, q, n, out);
}

// round 10
// speedup vs baseline: 1.1702x; 1.0052x over previous
#include <cuda_runtime.h>

#define NTHR 256
#define NBLK 888                          // 6 blocks/SM x 148 SMs, one wave
#define VPT  2
#define ITER_CHUNK (NBLK * NTHR * VPT)    // float4 per static grid-iteration
#define CHUNK_V4 (NTHR * VPT)             // 512 float4 per dynamic chunk
#define MAXC 16384

__device__ float        g_partials[NBLK];
__device__ float        g_chunk[MAXC];
__device__ unsigned int g_steal = 0;
__device__ unsigned int g_count = 0;

// Raw MUFU.LG2 — inputs guaranteed in [1e-4, 1-1e-4] (always normal).
__device__ __forceinline__ float lg2_raw(float x) {
    float r;
    asm("lg2.approx.ftz.f32 %0, %1;" : "=f"(r) : "f"(x));
    return r;
}

// FMA-pipe log2 (degree-7 Horner, lg2 units); offloads 1 of 4 logs from the
// ~87%-co-loaded MUFU pipe. Max abs err ~1.7e-4 lg2-units — inside gate.
__device__ __forceinline__ float lg2_poly(float x) {
    int   xi = __float_as_int(x);
    int   k  = xi - 0x3f3504f3;
    int   eb = k & 0xff800000;
    float m  = __int_as_float(xi - eb);
    float e  = (float)(eb >> 23);
    float f  = m - 1.0f;
    float r  =            0.20609929f;
    r = fmaf(r, f, -0.24044917f);
    r = fmaf(r, f,  0.28853901f);
    r = fmaf(r, f, -0.36067376f);
    r = fmaf(r, f,  0.48089835f);
    r = fmaf(r, f, -0.72134752f);
    r = fmaf(r, f,  1.44269504f);
    return fmaf(r, f, e);
}

// Binary KL in log2 units; 3 MUFU + 1 poly per element, two accumulators.
__device__ __forceinline__ void kl2_acc(float p, float q,
                                        float& accA, float& accB) {
    float omp = 1.0f - p;
    float omq = 1.0f - q;
    float d1  = lg2_raw(p)   - lg2_raw(q);
    float d2  = lg2_raw(omp) - lg2_poly(omq);
    accA = fmaf(p,   d1, accA);
    accB = fmaf(omp, d2, accB);
}

__device__ __forceinline__ void kl2_vec4(float4 a, float4 b,
                                         float& accA, float& accB) {
    kl2_acc(a.x, b.x, accA, accB);
    kl2_acc(a.y, b.y, accA, accB);
    kl2_acc(a.z, b.z, accA, accB);
    kl2_acc(a.w, b.w, accA, accB);
}

__global__ void __launch_bounds__(NTHR, 6)
kl_fused(const float* __restrict__ p, const float* __restrict__ q,
         int n, float* __restrict__ out) {
    const int nvec = n >> 2;
    const float4* __restrict__ p4 = reinterpret_cast<const float4*>(p);
    const float4* __restrict__ q4 = reinterpret_cast<const float4*>(q);

    const int tid  = threadIdx.x;
    const int lane = tid & 31;

    // ---- Work split: ~81% static (best-known loop), ~19% stolen chunks ----
    const int total_iters  = nvec / ITER_CHUNK;          // 18 at N=2^25
    const int static_iters = (total_iters * 13) >> 4;    // 14 (~79%)
    const int static_end   = static_iters * ITER_CHUNK;  // float4 index
    int nchunks = (nvec - static_end) / CHUNK_V4;
    if (nchunks > MAXC) nchunks = MAXC;
    const int dyn_end = static_end + nchunks * CHUNK_V4;

    float accA = 0.0f, accB = 0.0f;   // log2 units

    // ---- Static part: R6's pipelined loop (equal work per block) ----
    int idx = blockIdx.x * (NTHR * VPT) + tid;
    if (static_iters > 0) {
        float4 a0 = __ldcs(&p4[idx]);
        float4 a1 = __ldcs(&p4[idx + NTHR]);
        float4 b0 = __ldcs(&q4[idx]);
        float4 b1 = __ldcs(&q4[idx + NTHR]);
        for (int k = 1; k < static_iters; k++) {
            int nidx = idx + ITER_CHUNK;
            float4 na0 = __ldcs(&p4[nidx]);
            float4 na1 = __ldcs(&p4[nidx + NTHR]);
            float4 nb0 = __ldcs(&q4[nidx]);
            float4 nb1 = __ldcs(&q4[nidx + NTHR]);
            kl2_vec4(a0, b0, accA, accB);
            kl2_vec4(a1, b1, accA, accB);
            a0 = na0; a1 = na1; b0 = nb0; b1 = nb1;
            idx = nidx;
        }
        kl2_vec4(a0, b0, accA, accB);
        kl2_vec4(a1, b1, accA, accB);
    }

    // ---- Remainder beyond chunk coverage + scalar tail: last block ----
    if (blockIdx.x == gridDim.x - 1) {
        for (int i = dyn_end + tid; i < nvec; i += NTHR)
            kl2_vec4(__ldcs(&p4[i]), __ldcs(&q4[i]), accA, accB);
        for (int i = (nvec << 2) + tid; i < n; i += NTHR)
            kl2_acc(p[i], q[i], accA, accB);
    }

    // ---- Block reduce static partial -> g_partials[blockIdx.x] ----
    float acc = accA + accB;
    #pragma unroll
    for (int o = 16; o > 0; o >>= 1)
        acc += __shfl_down_sync(0xffffffffu, acc, o);
    __shared__ float s_red[NTHR / 32];
    if (lane == 0) s_red[tid >> 5] = acc;
    __syncthreads();
    if (tid == 0) {
        float t = 0.0f;
        #pragma unroll
        for (int w = 0; w < NTHR / 32; w++) t += s_red[w];
        g_partials[blockIdx.x] = t;
    }

    // ---- Dynamic tail-smoothing: steal 512-float4 chunks ----
    // Chunk partial depends only on chunk id (fixed thread->elem map, fixed
    // reduce tree) -> deterministic regardless of which block computes it.
    __shared__ unsigned int s_chunk;
    for (;;) {
        __syncthreads();                        // protect s_chunk / s_red reuse
        if (tid == 0) s_chunk = atomicAdd(&g_steal, 1u);
        __syncthreads();
        unsigned int c = s_chunk;
        if (c >= (unsigned int)nchunks) break;

        int base = static_end + (int)c * CHUNK_V4 + tid;
        float cA = 0.0f, cB = 0.0f;
        float4 a0 = __ldcs(&p4[base]);
        float4 a1 = __ldcs(&p4[base + NTHR]);
        float4 b0 = __ldcs(&q4[base]);
        float4 b1 = __ldcs(&q4[base + NTHR]);
        kl2_vec4(a0, b0, cA, cB);
        kl2_vec4(a1, b1, cA, cB);
        float cv = cA + cB;
        #pragma unroll
        for (int o = 16; o > 0; o >>= 1)
            cv += __shfl_down_sync(0xffffffffu, cv, o);
        if (lane == 0) s_red[tid >> 5] = cv;
        __syncthreads();
        if (tid == 0) {
            float t = 0.0f;
            #pragma unroll
            for (int w = 0; w < NTHR / 32; w++) t += s_red[w];
            g_chunk[c] = t;
        }
    }

    // ---- Completion + deterministic final reduce ----
    __threadfence();
    __syncthreads();
    __shared__ bool is_last;
    if (tid == 0) {
        // atomicInc wraps to 0 at gridDim.x-1 -> self-resetting across replays.
        unsigned int done = atomicInc(&g_count, gridDim.x - 1);
        is_last = (done == gridDim.x - 1);
    }
    __syncthreads();

    if (is_last) {
        __threadfence();
        double d = 0.0;
        for (int i = tid; i < NBLK; i += NTHR)          // fixed order
            d += (double)g_partials[i];
        for (int i = tid; i < nchunks; i += NTHR)       // fixed order
            d += (double)g_chunk[i];
        #pragma unroll
        for (int o = 16; o > 0; o >>= 1)
            d += __shfl_down_sync(0xffffffffu, d, o);
        __shared__ double sd[NTHR / 32];
        if (lane == 0) sd[tid >> 5] = d;
        __syncthreads();
        if (tid == 0) {
            double t = 0.0;
            #pragma unroll
            for (int w = 0; w < NTHR / 32; w++) t += sd[w];
            out[0] = (float)(t * 0.6931471805599453);   // log2 -> ln
            g_steal = 0;                                 // reset for replay
        }
    }
}

extern "C" void kernel_launch(void* const* d_in, const int* in_sizes, int n_in,
                              void* d_out, int out_size) {
    const float* p = (const float*)d_in[0];
    const float* q = (const float*)d_in[1];
    float* out = (float*)d_out;
    int n = in_sizes[0];

    kl_fused<<<NBLK, NTHR>>>(p, q, n, out);
}

// round 11
// speedup vs baseline: 1.2313x; 1.0522x over previous
#include <cuda_runtime.h>

#define NTHR 256
#define NBLK 1184                        // 8 blocks/SM x 148 SMs = one full wave

__device__ float        g_partials[NBLK];
__device__ unsigned int g_count = 0;

// Raw MUFU.LG2 — inputs guaranteed in [1e-4, 1-1e-4] (always normal).
__device__ __forceinline__ float lg2_raw(float x) {
    float r;
    asm("lg2.approx.ftz.f32 %0, %1;" : "=f"(r) : "f"(x));
    return r;
}

// FMA-pipe log2 (degree-7 Horner, lg2 units): offloads 1 of 4 logs from the
// MUFU pipe. Coefficients are immediates (no register cost). Max abs err
// ~1.7e-4 lg2-units -> far inside the 1e-3 gate.
__device__ __forceinline__ float lg2_poly(float x) {
    int   xi = __float_as_int(x);
    int   k  = xi - 0x3f3504f3;          // center mantissa at sqrt(2)
    int   eb = k & 0xff800000;
    float m  = __int_as_float(xi - eb);  // [0.7071, 1.4142)
    float e  = (float)(eb >> 23);
    float f  = m - 1.0f;
    float r  =            0.20609929f;
    r = fmaf(r, f, -0.24044917f);
    r = fmaf(r, f,  0.28853901f);
    r = fmaf(r, f, -0.36067376f);
    r = fmaf(r, f,  0.48089835f);
    r = fmaf(r, f, -0.72134752f);
    r = fmaf(r, f,  1.44269504f);
    return fmaf(r, f, e);
}

// Binary KL in log2 units; 3 MUFU + 1 poly per element, two accumulators.
__device__ __forceinline__ void kl2_acc(float p, float q,
                                        float& accA, float& accB) {
    float omp = 1.0f - p;
    float omq = 1.0f - q;
    float d1  = lg2_raw(p)   - lg2_raw(q);
    float d2  = lg2_raw(omp) - lg2_poly(omq);
    accA = fmaf(p,   d1, accA);
    accB = fmaf(omp, d2, accB);
}

__global__ void __launch_bounds__(NTHR, 8)   // cap 32 regs -> 64 warps/SM
kl_fused(const float* __restrict__ p, const float* __restrict__ q,
         int n, float* __restrict__ out) {
    const int nvec = n >> 2;
    const float4* __restrict__ p4 = reinterpret_cast<const float4*>(p);
    const float4* __restrict__ q4 = reinterpret_cast<const float4*>(q);

    float accA = 0.0f, accB = 0.0f;   // log2 units

    // Simple grid-stride, VPT=1: minimal live registers (fits 32-reg cap
    // without spill); latency hidden by 16 warps/SMSP.
    const int stride = NBLK * NTHR;
    for (int i = blockIdx.x * NTHR + threadIdx.x; i < nvec; i += stride) {
        float4 a = __ldcs(&p4[i]);
        float4 b = __ldcs(&q4[i]);
        kl2_acc(a.x, b.x, accA, accB);
        kl2_acc(a.y, b.y, accA, accB);
        kl2_acc(a.z, b.z, accA, accB);
        kl2_acc(a.w, b.w, accA, accB);
    }

    // Scalar tail (n % 4): last block only.
    if (blockIdx.x == gridDim.x - 1) {
        for (int i = (nvec << 2) + threadIdx.x; i < n; i += NTHR)
            kl2_acc(p[i], q[i], accA, accB);
    }

    float acc = (accA + accB) * 0.6931471805599453f;   // log2 -> ln, once

    // Block reduce (fixed tree -> deterministic)
    #pragma unroll
    for (int o = 16; o > 0; o >>= 1)
        acc += __shfl_down_sync(0xffffffffu, acc, o);
    __shared__ float s[NTHR / 32];
    if ((threadIdx.x & 31) == 0) s[threadIdx.x >> 5] = acc;
    __syncthreads();
    float bsum = 0.0f;
    if (threadIdx.x < 32) {
        bsum = (threadIdx.x < NTHR / 32) ? s[threadIdx.x] : 0.0f;
        #pragma unroll
        for (int o = (NTHR / 64); o > 0; o >>= 1)
            bsum += __shfl_down_sync(0xffffffffu, bsum, o);
    }

    __shared__ bool is_last;
    if (threadIdx.x == 0) {
        g_partials[blockIdx.x] = bsum;
        __threadfence();
        // atomicInc wraps to 0 at gridDim.x-1 -> self-resetting, graph-replay safe.
        unsigned int done = atomicInc(&g_count, gridDim.x - 1);
        is_last = (done == gridDim.x - 1);
    }
    __syncthreads();

    if (is_last) {
        // Deterministic fixed-order final reduce in fp64.
        double dacc = 0.0;
        for (int i = threadIdx.x; i < gridDim.x; i += NTHR)
            dacc += (double)g_partials[i];
        #pragma unroll
        for (int o = 16; o > 0; o >>= 1)
            dacc += __shfl_down_sync(0xffffffffu, dacc, o);
        __shared__ double sd[NTHR / 32];
        if ((threadIdx.x & 31) == 0) sd[threadIdx.x >> 5] = dacc;
        __syncthreads();
        if (threadIdx.x == 0) {
            double t = 0.0;
            #pragma unroll
            for (int w = 0; w < NTHR / 32; w++) t += sd[w];
            out[0] = (float)t;
        }
    }
}

extern "C" void kernel_launch(void* const* d_in, const int* in_sizes, int n_in,
                              void* d_out, int out_size) {
    const float* p = (const float*)d_in[0];
    const float* q = (const float*)d_in[1];
    float* out = (float*)d_out;
    int n = in_sizes[0];

    kl_fused<<<NBLK, NTHR>>>(p, q, n, out);
}